// round 10
// baseline (speedup 1.0000x reference)
#include <cuda_runtime.h>
#include <cuda_fp16.h>
#include <math.h>

// Problem constants
#define B_  4
#define L_  1024
#define D_  1024
#define DF_ 4096
#define E_  32768
#define R_  64
#define M_  (B_ * L_)
#define EPS_ 1e-6f

// Arch-feature gate: tcgen05 only exists in an arch-specific (sm_103a) pass.
// If the harness only emits compute_103 PTX, fall back to mma.sync.
#if defined(__CUDA_ARCH_FEAT_SM103_ALL) || defined(__CUDA_ARCH_FEAT_SM100_ALL) || defined(__CUDA_ARCH_SPECIFIC__)
#define TC_OK 1
#else
#define TC_OK 0
#endif

// ---------------------------------------------------------------------------
// Scratch
// ---------------------------------------------------------------------------
__device__ float  g_hsnorm[M_ * D_];
__device__ __half g_hsnorm_h[M_ * D_];
__device__ __half g_q_h[M_ * D_];
__device__ __half g_k_h[M_ * D_];
__device__ __half g_v_h[M_ * D_];
__device__ __half g_o_h[M_ * D_];
__device__ float  g_t1[M_ * D_];
__device__ float  g_out[M_ * D_];
__device__ __half g_out_h[M_ * D_];
__device__ __half g_h1_h[M_ * DF_];
__device__ float  g_f[M_ * D_];
__device__ float  g_score[B_ * E_];
__device__ int    g_perm[B_ * E_];
__device__ int    g_cnt[B_ * L_];
__device__ int    g_off[B_ * (L_ + 1)];
// edge-phase algebra buffers
__device__ float  g_T[M_ * R_];
__device__ float  g_term1[M_ * D_];
__device__ float  g_z[M_];
__device__ __half g_wn_h[M_ * R_];
// fp16 TRANSPOSED weights ([N,K] K-contig) + rel tables
__device__ __half g_wq_h[D_ * D_];
__device__ __half g_wk_h[D_ * D_];
__device__ __half g_wv_h[D_ * D_];
__device__ __half g_wo_h[D_ * D_];
__device__ __half g_w1_h[D_ * DF_];
__device__ __half g_w2_h[DF_ * D_];
__device__ __half g_rel_t_h[D_ * R_];  // [d][r] = rel[r][d]

// ---------------------------------------------------------------------------
// fp32 [K,N] -> fp16 [N,K] transpose
// ---------------------------------------------------------------------------
__global__ void transpose_f2h(const float* __restrict__ src, __half* __restrict__ dst,
                              int K, int N) {
    __shared__ float t[32][33];
    int n0 = blockIdx.x * 32, k0 = blockIdx.y * 32;
    int tx = threadIdx.x, ty = threadIdx.y;   // 32 x 8
    #pragma unroll
    for (int i = 0; i < 4; i++)
        t[ty + 8 * i][tx] = src[(size_t)(k0 + ty + 8 * i) * N + n0 + tx];
    __syncthreads();
    #pragma unroll
    for (int i = 0; i < 4; i++)
        dst[(size_t)(n0 + ty + 8 * i) * K + k0 + tx] = __float2half(t[tx][ty + 8 * i]);
}

__global__ void rel_transpose(const float* __restrict__ rel) {
    int idx = blockIdx.x * 256 + threadIdx.x;
    int k = idx >> 6, n = idx & 63;
    g_rel_t_h[idx] = __float2half(rel[n * D_ + k]);
}

// ---------------------------------------------------------------------------
// LayerNorm helpers
// ---------------------------------------------------------------------------
__device__ __forceinline__ void row_moments(float4 v, float& mean, float& rstd,
                                            float* sh1, float* sh2) {
    float s  = v.x + v.y + v.z + v.w;
    float sq = v.x * v.x + v.y * v.y + v.z * v.z + v.w * v.w;
    #pragma unroll
    for (int o = 16; o; o >>= 1) {
        s  += __shfl_xor_sync(0xffffffffu, s, o);
        sq += __shfl_xor_sync(0xffffffffu, sq, o);
    }
    int warp = threadIdx.x >> 5, lane = threadIdx.x & 31;
    if (lane == 0) { sh1[warp] = s; sh2[warp] = sq; }
    __syncthreads();
    if (threadIdx.x < 8) {
        s = sh1[threadIdx.x]; sq = sh2[threadIdx.x];
        #pragma unroll
        for (int o = 4; o; o >>= 1) {
            s  += __shfl_xor_sync(0xffu, s, o);
            sq += __shfl_xor_sync(0xffu, sq, o);
        }
        if (threadIdx.x == 0) { sh1[0] = s; sh2[0] = sq; }
    }
    __syncthreads();
    mean = sh1[0] * (1.0f / D_);
    float var = sh2[0] * (1.0f / D_) - mean * mean;
    rstd = rsqrtf(var + EPS_);
}

__global__ void ln_dual_kernel(const float* __restrict__ x, const float* __restrict__ g,
                               const float* __restrict__ b, float* __restrict__ y,
                               __half* y16) {
    __shared__ float sh1[8], sh2[8];
    size_t row = blockIdx.x;
    int t = threadIdx.x;
    float4 v = ((const float4*)(x + row * D_))[t];
    float mean, rstd;
    row_moments(v, mean, rstd, sh1, sh2);
    float4 gv = ((const float4*)g)[t];
    float4 bv = ((const float4*)b)[t];
    float4 o;
    o.x = (v.x - mean) * rstd * gv.x + bv.x;
    o.y = (v.y - mean) * rstd * gv.y + bv.y;
    o.z = (v.z - mean) * rstd * gv.z + bv.z;
    o.w = (v.w - mean) * rstd * gv.w + bv.w;
    ((float4*)(y + row * D_))[t] = o;
    if (y16) {
        __half2 h0 = __floats2half2_rn(o.x, o.y);
        __half2 h1 = __floats2half2_rn(o.z, o.w);
        __half2* p = (__half2*)(y16 + row * D_);
        p[2 * t] = h0; p[2 * t + 1] = h1;
    }
}

__global__ void ln_elu_res_kernel(const float* __restrict__ x, const float* __restrict__ g,
                                  const float* __restrict__ b,
                                  const float* __restrict__ hidden,
                                  float* __restrict__ out) {
    __shared__ float sh1[8], sh2[8];
    size_t row = blockIdx.x;
    int t = threadIdx.x;
    float4 v = ((const float4*)(x + row * D_))[t];
    float mean, rstd;
    row_moments(v, mean, rstd, sh1, sh2);
    float4 gv = ((const float4*)g)[t];
    float4 bv = ((const float4*)b)[t];
    float4 hv = ((const float4*)(hidden + row * D_))[t];
    float n0 = (v.x - mean) * rstd * gv.x + bv.x;
    float n1 = (v.y - mean) * rstd * gv.y + bv.y;
    float n2 = (v.z - mean) * rstd * gv.z + bv.z;
    float n3 = (v.w - mean) * rstd * gv.w + bv.w;
    float4 o;
    o.x = hv.x + (n0 > 0.f ? n0 : expm1f(n0));
    o.y = hv.y + (n1 > 0.f ? n1 : expm1f(n1));
    o.z = hv.z + (n2 > 0.f ? n2 : expm1f(n2));
    o.w = hv.w + (n3 > 0.f ? n3 : expm1f(n3));
    ((float4*)(out + row * D_))[t] = o;
}

// ---------------------------------------------------------------------------
// Common GEMM bits
// ---------------------------------------------------------------------------
#define CP16(dst, src) \
    asm volatile("cp.async.cg.shared.global [%0], [%1], 16;\n" :: "r"(dst), "l"(src))

__device__ __forceinline__ void mma_f16(float* c, const unsigned* a, const unsigned* b) {
    asm volatile(
        "mma.sync.aligned.m16n8k16.row.col.f32.f16.f16.f32 "
        "{%0,%1,%2,%3}, {%4,%5,%6,%7}, {%8,%9}, {%0,%1,%2,%3};"
        : "+f"(c[0]), "+f"(c[1]), "+f"(c[2]), "+f"(c[3])
        : "r"(a[0]), "r"(a[1]), "r"(a[2]), "r"(a[3]), "r"(b[0]), "r"(b[1]));
}

// GEMM smem budget: tc path needs 3*32KB + 1KB; fallback needs 60KB. Use max.
#define GEMM_SMEM 99328

#if TC_OK
// ---- tcgen05 plumbing (compiled only in arch-specific pass) ----
__device__ __forceinline__ unsigned elect_one_pred() {
    unsigned pred;
    asm volatile(
        "{\n\t.reg .pred p;\n\t"
        "elect.sync _|p, 0xFFFFFFFF;\n\t"
        "selp.b32 %0, 1, 0, p;\n\t}"
        : "=r"(pred));
    return pred;
}

#define MBARRIER_INIT(addr, count) \
    asm volatile("mbarrier.init.shared.b64 [%0], %1;" :: "r"(addr), "r"((unsigned)(count)) : "memory")

#define MBARRIER_WAIT_PARITY(mbar_smem_addr, phase_parity) do { \
    unsigned _mbar = (unsigned)(mbar_smem_addr); \
    unsigned _parity = (unsigned)(phase_parity); \
    unsigned _done; \
    asm volatile( \
        "{\n\t.reg .pred p;\n\t" \
        "mbarrier.try_wait.parity.acquire.cta.shared::cta.b64 p, [%1], %2;\n\t" \
        "selp.b32 %0, 1, 0, p;\n\t}" \
        : "=r"(_done) : "r"(_mbar), "r"(_parity) : "memory"); \
    if (!_done) { \
        asm volatile( \
            "{\n\t.reg .pred P1;\n\t" \
            "WAIT_LOOP_%=:\n\t" \
            "mbarrier.try_wait.parity.acquire.cta.shared::cta.b64 P1, [%0], %1, 0x989680;\n\t" \
            "@P1 bra.uni WAIT_DONE_%=;\n\t" \
            "bra.uni WAIT_LOOP_%=;\n\t" \
            "WAIT_DONE_%=:\n\t}" \
            :: "r"(_mbar), "r"(_parity) : "memory"); \
    } \
} while (0)

#define TCGEN05_LD_X32(r, addr) \
    asm volatile( \
        "tcgen05.ld.sync.aligned.32x32b.x32.b32 " \
        "{%0,%1,%2,%3,%4,%5,%6,%7,%8,%9,%10,%11,%12,%13,%14,%15," \
        "%16,%17,%18,%19,%20,%21,%22,%23,%24,%25,%26,%27,%28,%29,%30,%31}, [%32];" \
        : "=r"((r)[0]), "=r"((r)[1]), "=r"((r)[2]), "=r"((r)[3]), \
          "=r"((r)[4]), "=r"((r)[5]), "=r"((r)[6]), "=r"((r)[7]), \
          "=r"((r)[8]), "=r"((r)[9]), "=r"((r)[10]), "=r"((r)[11]), \
          "=r"((r)[12]), "=r"((r)[13]), "=r"((r)[14]), "=r"((r)[15]), \
          "=r"((r)[16]), "=r"((r)[17]), "=r"((r)[18]), "=r"((r)[19]), \
          "=r"((r)[20]), "=r"((r)[21]), "=r"((r)[22]), "=r"((r)[23]), \
          "=r"((r)[24]), "=r"((r)[25]), "=r"((r)[26]), "=r"((r)[27]), \
          "=r"((r)[28]), "=r"((r)[29]), "=r"((r)[30]), "=r"((r)[31]) \
        : "r"(addr))

__device__ __forceinline__ void tc_mma_f16_ss(unsigned d_tmem, unsigned long long a_desc,
                                              unsigned long long b_desc, unsigned idesc,
                                              bool accum) {
    unsigned en = accum ? 1u : 0u;
    asm volatile(
        "{\n\t.reg .pred p;\n\t"
        "setp.ne.u32 p, %4, 0;\n\t"
        "tcgen05.mma.cta_group::1.kind::f16 [%0], %1, %2, %3, {%5,%5,%5,%5}, p;\n\t}"
        :: "r"(d_tmem), "l"(a_desc), "l"(b_desc), "r"(idesc), "r"(en), "r"(0u)
        : "memory");
}

__device__ __forceinline__ unsigned long long make_desc(unsigned addr) {
    const unsigned long long base =
        (2ULL << 61) | (1ULL << 46) | (64ULL << 32) | (1ULL << 16);
    return base | ((unsigned long long)(addr >> 4) & 0x3FFFULL);
}

#define TC_IDESC ((1u << 4) | ((128u / 8) << 17) | ((128u / 16) << 24))
#define TC_STAGE 32768
#endif  // TC_OK

// Fallback mma.sync constants: 4 warps, warp 64x64, BK=32, 3 stages.
#define F_APW  20                    // pitch in 32-bit words (32 data halves + 8 pad)
#define F_ASTG (128 * F_APW)         // 2560 words per tile per stage
#define F_NST  3

// ---------------------------------------------------------------------------
// Unified GEMM body: C[M,N] = A[M,K] @ Bt[N,K]^T (+bias)(+res)(+relu)
// ---------------------------------------------------------------------------
template <bool RELU, bool OUTHALF>
__device__ __forceinline__ void gemm_body(
    const __half* __restrict__ A, const __half* __restrict__ Bt,
    const float* bias, const float* res, float* C32, __half* C16,
    int N, int K, int bm, int bn) {
#if TC_OK
    // ======================= tcgen05 path =======================
    extern __shared__ char dsm[];
    unsigned raw = (unsigned)__cvta_generic_to_shared(dsm);
    unsigned base = (raw + 1023) & ~1023u;
    __shared__ unsigned s_tmem;
    __shared__ __align__(8) unsigned long long s_mbar[3];

    int tid = threadIdx.x, warp = tid >> 5, lane = tid & 31;
    unsigned mb0 = (unsigned)__cvta_generic_to_shared(&s_mbar[0]);
    unsigned mb1 = mb0 + 8, mb2 = mb0 + 16;

    if (tid == 0) {
        MBARRIER_INIT(mb0, 1);
        MBARRIER_INIT(mb1, 1);
        MBARRIER_INIT(mb2, 1);
    }
    if (warp == 0) {
        asm volatile("tcgen05.alloc.cta_group::1.sync.aligned.shared::cta.b32 [%0], %1;"
                     :: "r"((unsigned)__cvta_generic_to_shared(&s_tmem)), "r"(128u) : "memory");
        asm volatile("tcgen05.relinquish_alloc_permit.cta_group::1.sync.aligned;");
    }
    __syncthreads();
    unsigned tmem = s_tmem;

    int row = tid;                      // 128 threads, one row each
    unsigned off[8];
    #pragma unroll
    for (int j = 0; j < 8; j++) {
        unsigned bo = row * 128 + j * 16;
        off[j] = bo ^ ((bo >> 3) & 0x70);
    }
    const __half* aptr = A + (size_t)(bm + row) * K;
    const __half* bptr = Bt + (size_t)(bn + row) * K;

    int ntiles = K >> 6;

    auto load_chunk = [&](int c, int st) {
        unsigned ab = base + st * TC_STAGE;
        unsigned bb = ab + 16384;
        const __half* ap = aptr + c * 64;
        const __half* bp = bptr + c * 64;
        #pragma unroll
        for (int j = 0; j < 8; j++) {
            CP16(ab + off[j], ap + j * 8);
            CP16(bb + off[j], bp + j * 8);
        }
    };

    if (0 < ntiles) load_chunk(0, 0);
    asm volatile("cp.async.commit_group;\n");
    if (1 < ntiles) load_chunk(1, 1);
    asm volatile("cp.async.commit_group;\n");

    int ph0 = 0, ph1 = 0, ph2 = 0;
    for (int c = 0; c < ntiles; c++) {
        int nx = c + 2;
        if (nx < ntiles) {
            int st = nx % 3;
            if (nx >= 3) {
                if (st == 0)      { MBARRIER_WAIT_PARITY(mb0, ph0); ph0 ^= 1; }
                else if (st == 1) { MBARRIER_WAIT_PARITY(mb1, ph1); ph1 ^= 1; }
                else              { MBARRIER_WAIT_PARITY(mb2, ph2); ph2 ^= 1; }
            }
            load_chunk(nx, st);
        }
        asm volatile("cp.async.commit_group;\n");
        asm volatile("cp.async.wait_group 2;\n");
        asm volatile("fence.proxy.async.shared::cta;" ::: "memory");
        __syncthreads();
        if (warp == 0) {
            asm volatile("tcgen05.fence::after_thread_sync;" ::: "memory");
            if (elect_one_pred()) {
                int st = c % 3;
                unsigned ab = base + st * TC_STAGE;
                unsigned long long ad = make_desc(ab);
                unsigned long long bd = make_desc(ab + 16384);
                #pragma unroll
                for (int s2 = 0; s2 < 4; s2++)
                    tc_mma_f16_ss(tmem, ad + s2 * 2, bd + s2 * 2, TC_IDESC,
                                  !(c == 0 && s2 == 0));
                unsigned mbx = (st == 0) ? mb0 : (st == 1) ? mb1 : mb2;
                asm volatile("tcgen05.commit.cta_group::1.mbarrier::arrive::one.shared::cluster.b64 [%0];"
                             :: "r"(mbx) : "memory");
            }
        }
    }
    {
        int sl = (ntiles - 1) % 3;
        if (sl == 0)      MBARRIER_WAIT_PARITY(mb0, ph0);
        else if (sl == 1) MBARRIER_WAIT_PARITY(mb1, ph1);
        else              MBARRIER_WAIT_PARITY(mb2, ph2);
    }
    asm volatile("tcgen05.fence::after_thread_sync;" ::: "memory");

    // Epilogue: each warp owns its 32-lane subpartition; two 64-col batches.
    int m = bm + warp * 32 + lane;
    #pragma unroll
    for (int half = 0; half < 2; half++) {
        unsigned dreg[64];
        TCGEN05_LD_X32(dreg, tmem + half * 64);
        TCGEN05_LD_X32(dreg + 32, tmem + half * 64 + 32);
        asm volatile("tcgen05.wait::ld.sync.aligned;" ::: "memory");
        int colb = bn + half * 64;
        #pragma unroll
        for (int c4 = 0; c4 < 64; c4 += 4) {
            float v0 = __uint_as_float(dreg[c4]);
            float v1 = __uint_as_float(dreg[c4 + 1]);
            float v2 = __uint_as_float(dreg[c4 + 2]);
            float v3 = __uint_as_float(dreg[c4 + 3]);
            if (bias) {
                float4 bb = *(const float4*)(bias + colb + c4);
                v0 += bb.x; v1 += bb.y; v2 += bb.z; v3 += bb.w;
            }
            if (res) {
                float4 rr = *(const float4*)(res + (size_t)m * N + colb + c4);
                v0 += rr.x; v1 += rr.y; v2 += rr.z; v3 += rr.w;
            }
            if (RELU) {
                v0 = fmaxf(v0, 0.f); v1 = fmaxf(v1, 0.f);
                v2 = fmaxf(v2, 0.f); v3 = fmaxf(v3, 0.f);
            }
            if (OUTHALF) {
                *(__half2*)(C16 + (size_t)m * N + colb + c4)     = __floats2half2_rn(v0, v1);
                *(__half2*)(C16 + (size_t)m * N + colb + c4 + 2) = __floats2half2_rn(v2, v3);
            } else {
                *(float4*)(C32 + (size_t)m * N + colb + c4) = make_float4(v0, v1, v2, v3);
            }
        }
    }
    asm volatile("tcgen05.fence::before_thread_sync;" ::: "memory");
    __syncthreads();
    if (warp == 0)
        asm volatile("tcgen05.dealloc.cta_group::1.sync.aligned.b32 %0, %1;"
                     :: "r"(tmem), "r"(128u));
#else
    // ======================= mma.sync fallback =======================
    extern __shared__ unsigned sm[];
    unsigned* As = sm;                  // [3][128][F_APW]
    unsigned* Bs = sm + F_NST * F_ASTG; // [3][128][F_APW]
    int tid = threadIdx.x;
    int warp = tid >> 5, lane = tid & 31;
    int g = lane >> 2, tg = lane & 3;
    int wm = (warp & 1) * 64, wn = (warp >> 1) * 64;

    int row = tid;                      // one row per thread
    const __half* aptr = A + (size_t)(bm + row) * K;
    const __half* bptr = Bt + (size_t)(bn + row) * K;
    unsigned a_dst = (unsigned)__cvta_generic_to_shared(As + row * F_APW);
    unsigned b_dst = (unsigned)__cvta_generic_to_shared(Bs + row * F_APW);

    // ldmatrix lane base (non-trans, both operands): rows k-contig
    int quad = lane >> 3, j8 = lane & 7;
    int lrow = (quad & 1) * 8 + j8;
    int lcb  = (quad >> 1) * 16;        // byte offset within row

    int ntiles = K >> 5;

    auto load_tile = [&](int c, int st) {
        unsigned ad = a_dst + st * F_ASTG * 4;
        unsigned bd = b_dst + st * F_ASTG * 4;
        const __half* ap = aptr + c * 32;
        const __half* bp = bptr + c * 32;
        #pragma unroll
        for (int j = 0; j < 4; j++) {
            CP16(ad + j * 16, ap + j * 8);
            CP16(bd + j * 16, bp + j * 8);
        }
    };

    if (0 < ntiles) load_tile(0, 0);
    asm volatile("cp.async.commit_group;\n");
    if (1 < ntiles) load_tile(1, 1);
    asm volatile("cp.async.commit_group;\n");

    float acc[4][8][4];
    #pragma unroll
    for (int mt = 0; mt < 4; mt++)
        #pragma unroll
        for (int nt = 0; nt < 8; nt++)
            #pragma unroll
            for (int r = 0; r < 4; r++) acc[mt][nt][r] = 0.f;

    unsigned a_frag = (unsigned)__cvta_generic_to_shared(As) + (wm + lrow) * F_APW * 4 + lcb;
    unsigned b_frag = (unsigned)__cvta_generic_to_shared(Bs) + (wn + lrow) * F_APW * 4 + lcb;

    for (int kt = 0; kt < ntiles; kt++) {
        asm volatile("cp.async.wait_group 1;\n");
        __syncthreads();
        int nx = kt + 2;
        if (nx < ntiles) load_tile(nx, nx % F_NST);
        asm volatile("cp.async.commit_group;\n");

        int cur = kt % F_NST;
        unsigned ab = a_frag + cur * F_ASTG * 4;
        unsigned bb = b_frag + cur * F_ASTG * 4;
        #pragma unroll
        for (int ks = 0; ks < 2; ks++) {
            unsigned af[4][4];
            #pragma unroll
            for (int mt = 0; mt < 4; mt++) {
                unsigned addr = ab + mt * 16 * F_APW * 4 + ks * 32;
                asm volatile(
                    "ldmatrix.sync.aligned.m8n8.x4.shared.b16 {%0,%1,%2,%3}, [%4];"
                    : "=r"(af[mt][0]), "=r"(af[mt][1]), "=r"(af[mt][2]), "=r"(af[mt][3])
                    : "r"(addr));
            }
            unsigned bf[8][2];
            #pragma unroll
            for (int nb = 0; nb < 4; nb++) {
                unsigned q0, q1, q2, q3;
                unsigned addr = bb + nb * 16 * F_APW * 4 + ks * 32;
                asm volatile(
                    "ldmatrix.sync.aligned.m8n8.x4.shared.b16 {%0,%1,%2,%3}, [%4];"
                    : "=r"(q0), "=r"(q1), "=r"(q2), "=r"(q3)
                    : "r"(addr));
                bf[2 * nb][0] = q0; bf[2 * nb][1] = q2;
                bf[2 * nb + 1][0] = q1; bf[2 * nb + 1][1] = q3;
            }
            #pragma unroll
            for (int mt = 0; mt < 4; mt++)
                #pragma unroll
                for (int nt = 0; nt < 8; nt++)
                    mma_f16(acc[mt][nt], af[mt], bf[nt]);
        }
    }

    #pragma unroll
    for (int mt = 0; mt < 4; mt++) {
        #pragma unroll
        for (int nt = 0; nt < 8; nt++) {
            int col = bn + wn + nt * 8 + tg * 2;
            #pragma unroll
            for (int h = 0; h < 2; h++) {
                int rr2 = bm + wm + mt * 16 + g + h * 8;
                float vx = acc[mt][nt][2 * h];
                float vy = acc[mt][nt][2 * h + 1];
                if (bias) {
                    float2 bb2 = *(const float2*)(bias + col);
                    vx += bb2.x; vy += bb2.y;
                }
                if (res) {
                    float2 rv = *(const float2*)(res + (size_t)rr2 * N + col);
                    vx += rv.x; vy += rv.y;
                }
                if (RELU) { vx = fmaxf(vx, 0.f); vy = fmaxf(vy, 0.f); }
                if (OUTHALF)
                    *(__half2*)(C16 + (size_t)rr2 * N + col) = __floats2half2_rn(vx, vy);
                else
                    *(float2*)(C32 + (size_t)rr2 * N + col) = make_float2(vx, vy);
            }
        }
    }
#endif
}

template <bool RELU, bool OUTHALF>
__global__ __launch_bounds__(128, 2) void gemm_uni(
    const __half* __restrict__ A, const __half* __restrict__ Bt,
    const float* bias, const float* res, float* C32, __half* C16,
    int M, int N, int K) {
    gemm_body<RELU, OUTHALF>(A, Bt, bias, res, C32, C16, N, K,
                             blockIdx.y * 128, blockIdx.x * 128);
}

struct QKVArgs {
    const __half* Bt[3];
    const float* bias[3];
    __half* C[3];
};

__global__ __launch_bounds__(128, 2) void gemm_uni_qkv(
    const __half* __restrict__ A, QKVArgs args, int M, int N, int K) {
    int z = blockIdx.z;
    gemm_body<false, true>(A, args.Bt[z], args.bias[z], nullptr, nullptr,
                           args.C[z], N, K, blockIdx.y * 128, blockIdx.x * 128);
}

// ---------------------------------------------------------------------------
// Small-N GEMM (mma.sync, 256 thr): T[M,64] = q[M,1024] @ rel_t[1024,64]
// ---------------------------------------------------------------------------
#define APW   20
#define ASTG  (128 * APW)
#define NSTAGE 3
#define PB64 72
#define BSTG64 (32 * PB64 / 2)

__global__ __launch_bounds__(256, 2) void gemm_T64(
    const __half* __restrict__ A, const __half* __restrict__ Bm,
    float* __restrict__ C, int K) {
    __shared__ unsigned smT[NSTAGE * (ASTG + BSTG64)];
    unsigned* As = smT;
    unsigned* Bs = smT + NSTAGE * ASTG;
    const int N = R_;
    int tid = threadIdx.x;
    int warp = tid >> 5, lane = tid & 31;
    int g = lane >> 2, tg = lane & 3;
    int wm = (warp & 3) * 32, wn = (warp >> 2) * 32;
    int bm = blockIdx.y * 128;

    int arow = tid >> 1;
    const __half* aptr = A + (size_t)(bm + arow) * K + (tid & 1) * 16;
    unsigned a_dst = (unsigned)__cvta_generic_to_shared(As + arow * APW + (tid & 1) * 8);
    int brow = tid >> 3, bc = (tid & 7) * 8;
    const __half* bptr = Bm + (size_t)brow * N + bc;
    unsigned b_dst = (unsigned)__cvta_generic_to_shared((__half*)Bs + brow * PB64 + bc);

    int quad = lane >> 3, j = lane & 7;
    int lrow = (quad & 1) * 8 + j;
    int lcol = wn + (quad >> 1) * 8;
    unsigned b_frag_base = (unsigned)__cvta_generic_to_shared((__half*)Bs + lrow * PB64 + lcol);

    int ntiles = K >> 5;
    #pragma unroll
    for (int s = 0; s < NSTAGE - 1; s++) {
        unsigned ad = a_dst + s * ASTG * 4;
        unsigned bd = b_dst + s * BSTG64 * 4;
        CP16(ad, aptr + s * 32); CP16(ad + 16, aptr + s * 32 + 8);
        CP16(bd, bptr + (size_t)s * 32 * N);
        asm volatile("cp.async.commit_group;\n");
    }

    float acc[2][4][4];
    #pragma unroll
    for (int mt = 0; mt < 2; mt++)
        #pragma unroll
        for (int nt = 0; nt < 4; nt++)
            #pragma unroll
            for (int r = 0; r < 4; r++) acc[mt][nt][r] = 0.f;

    for (int kt = 0; kt < ntiles; kt++) {
        asm volatile("cp.async.wait_group %0;\n" :: "n"(NSTAGE - 2));
        __syncthreads();
        int nx = kt + NSTAGE - 1;
        if (nx < ntiles) {
            int st = nx % NSTAGE;
            unsigned ad = a_dst + st * ASTG * 4;
            unsigned bd = b_dst + st * BSTG64 * 4;
            CP16(ad, aptr + nx * 32); CP16(ad + 16, aptr + nx * 32 + 8);
            CP16(bd, bptr + (size_t)nx * 32 * N);
        }
        asm volatile("cp.async.commit_group;\n");

        int cur = kt % NSTAGE;
        const unsigned* Ab = As + cur * ASTG;
        unsigned bsm = b_frag_base + cur * BSTG64 * 4;
        #pragma unroll
        for (int ks = 0; ks < 2; ks++) {
            unsigned af[2][4];
            #pragma unroll
            for (int mt = 0; mt < 2; mt++) {
                const unsigned* p = Ab + (wm + mt * 16 + g) * APW + ks * 8 + tg;
                af[mt][0] = p[0];
                af[mt][1] = p[8 * APW];
                af[mt][2] = p[4];
                af[mt][3] = p[8 * APW + 4];
            }
            unsigned bf[4][2];
            #pragma unroll
            for (int nb = 0; nb < 2; nb++) {
                unsigned addr = bsm + ks * 16 * (PB64 * 2) + nb * 32;
                asm volatile(
                    "ldmatrix.sync.aligned.m8n8.x4.trans.shared.b16 {%0,%1,%2,%3}, [%4];"
                    : "=r"(bf[2 * nb][0]), "=r"(bf[2 * nb][1]),
                      "=r"(bf[2 * nb + 1][0]), "=r"(bf[2 * nb + 1][1])
                    : "r"(addr));
            }
            #pragma unroll
            for (int mt = 0; mt < 2; mt++)
                #pragma unroll
                for (int nt = 0; nt < 4; nt++)
                    mma_f16(acc[mt][nt], af[mt], bf[nt]);
        }
    }

    #pragma unroll
    for (int mt = 0; mt < 2; mt++)
        #pragma unroll
        for (int nt = 0; nt < 4; nt++) {
            int col = wn + nt * 8 + tg * 2;
            #pragma unroll
            for (int h = 0; h < 2; h++) {
                int row = bm + wm + mt * 16 + g + h * 8;
                *(float2*)(C + (size_t)row * N + col) =
                    make_float2(acc[mt][nt][2 * h], acc[mt][nt][2 * h + 1]);
            }
        }
}

// ---------------------------------------------------------------------------
// Edge scores: k[src].q[dst] + T[dst,rel]
// ---------------------------------------------------------------------------
__global__ void score_kernel(const __half* __restrict__ Q, const __half* __restrict__ Km,
                             const float* __restrict__ T,
                             const int* __restrict__ src, const int* __restrict__ dst,
                             const int* __restrict__ rel, float* __restrict__ score) {
    int idx = blockIdx.x * 4 + threadIdx.y;
    int b = idx >> 15;
    int lane = threadIdx.x;
    int s = src[idx], d = dst[idx], r = rel[idx];
    const __half* kr = Km + ((size_t)b * L_ + s) * D_;
    const __half* qr = Q + ((size_t)b * L_ + d) * D_;
    float acc = 0.f;
    #pragma unroll
    for (int i = 0; i < 4; i++) {
        int c = (lane + 32 * i) * 8;
        uint4 kv = *(const uint4*)(kr + c);
        uint4 qv = *(const uint4*)(qr + c);
        const __half2* kh = (const __half2*)&kv;
        const __half2* qh = (const __half2*)&qv;
        #pragma unroll
        for (int j = 0; j < 4; j++) {
            float2 kf = __half22float2(kh[j]);
            float2 qf = __half22float2(qh[j]);
            acc = fmaf(kf.x, qf.x, acc);
            acc = fmaf(kf.y, qf.y, acc);
        }
    }
    #pragma unroll
    for (int o = 16; o; o >>= 1) acc += __shfl_xor_sync(0xffffffffu, acc, o);
    if (lane == 0) {
        float sc = (acc + T[((size_t)b * L_ + d) * R_ + r]) * 0.03125f;
        sc = fminf(fmaxf(sc, -10.f), 10.f);
        score[idx] = expf(sc);
    }
}

// ---------------------------------------------------------------------------
// Deterministic binning
// ---------------------------------------------------------------------------
__global__ void zero_cnt_kernel() {
    int i = blockIdx.x * 256 + threadIdx.x;
    if (i < B_ * L_) g_cnt[i] = 0;
}

__global__ void hist_kernel(const int* __restrict__ edge_dst) {
    int idx = blockIdx.x * 256 + threadIdx.x;
    if (idx < B_ * E_) atomicAdd(&g_cnt[(idx >> 15) * L_ + edge_dst[idx]], 1);
}

__global__ void scan_kernel() {
    int b = blockIdx.x, t = threadIdx.x;
    __shared__ int s[L_];
    int c = g_cnt[b * L_ + t];
    s[t] = c;
    __syncthreads();
    for (int off = 1; off < L_; off <<= 1) {
        int v = (t >= off) ? s[t - off] : 0;
        __syncthreads();
        s[t] += v;
        __syncthreads();
    }
    g_off[b * (L_ + 1) + t] = s[t] - c;
    if (t == L_ - 1) g_off[b * (L_ + 1) + L_] = s[t];
}

__global__ void fill_block_kernel(const int* __restrict__ edge_dst) {
    __shared__ int sd[1024];
    int b = blockIdx.x >> 7;
    int nodebase = (blockIdx.x & 127) * 8;
    int warp = threadIdx.x >> 5, lane = threadIdx.x & 31;
    int node = nodebase + warp;
    int w = g_off[b * (L_ + 1) + node];
    int* pb = g_perm + b * E_;
    const int* dv = edge_dst + b * E_;
    for (int base = 0; base < E_; base += 1024) {
        __syncthreads();
        #pragma unroll
        for (int i = 0; i < 4; i++) sd[threadIdx.x + 256 * i] = dv[base + threadIdx.x + 256 * i];
        __syncthreads();
        for (int c = 0; c < 1024; c += 32) {
            int d = sd[c + lane];
            unsigned m = __ballot_sync(0xffffffffu, d == node);
            if (d == node) pb[w + __popc(m & ((1u << lane) - 1))] = base + c + lane;
            w += __popc(m);
        }
    }
}

// ---------------------------------------------------------------------------
// agg1: term1 = (sum s*v[src]) / z, and z per dst
// ---------------------------------------------------------------------------
__global__ void agg1_kernel(const __half* __restrict__ V,
                            const int* __restrict__ src,
                            const float* __restrict__ score) {
    int node = blockIdx.x, b = blockIdx.y;
    int t = threadIdx.x;
    int beg = g_off[b * (L_ + 1) + node];
    int end = g_off[b * (L_ + 1) + node + 1];
    const int* pb = g_perm + b * E_;
    float4 acc = make_float4(0.f, 0.f, 0.f, 0.f);
    float z = 0.f;
    for (int i = beg; i < end; i++) {
        int e = pb[i];
        float s = score[b * E_ + e];
        int sn = src[b * E_ + e];
        uint2 vw = *(const uint2*)(V + ((size_t)b * L_ + sn) * D_ + 4 * t);
        const __half2* vh = (const __half2*)&vw;
        float2 v0 = __half22float2(vh[0]), v1 = __half22float2(vh[1]);
        acc.x = fmaf(s, v0.x, acc.x);
        acc.y = fmaf(s, v0.y, acc.y);
        acc.z = fmaf(s, v1.x, acc.z);
        acc.w = fmaf(s, v1.y, acc.w);
        z += s;
    }
    float inv = 1.0f / z;
    *(float4*)(g_term1 + ((size_t)b * L_ + node) * D_ + 4 * t) =
        make_float4(acc.x * inv, acc.y * inv, acc.z * inv, acc.w * inv);
    if (t == 0) g_z[b * L_ + node] = z;
}

__global__ void wn_kernel(const int* __restrict__ rel, const float* __restrict__ score) {
    int node = blockIdx.x, b = blockIdx.y;
    int t = threadIdx.x;   // 0..63
    int beg = g_off[b * (L_ + 1) + node];
    int end = g_off[b * (L_ + 1) + node + 1];
    const int* pb = g_perm + b * E_;
    float W = 0.f;
    for (int i = beg; i < end; i++) {
        int e = pb[i];
        float s = score[b * E_ + e];
        int r = rel[b * E_ + e];
        if (r == t) W += s;
    }
    float z = g_z[b * L_ + node];
    g_wn_h[((size_t)b * L_ + node) * R_ + t] = __float2half(W / z);
}

// ---------------------------------------------------------------------------
// Launch
// ---------------------------------------------------------------------------
extern "C" void kernel_launch(void* const* d_in, const int* in_sizes, int n_in,
                              void* d_out, int out_size) {
    const float* hidden  = (const float*)d_in[0];
    const float* rel_tab = (const float*)d_in[1];
    const float* Wq = (const float*)d_in[2];
    const float* bq = (const float*)d_in[3];
    const float* Wk = (const float*)d_in[4];
    const float* Wv = (const float*)d_in[5];
    const float* Wo = (const float*)d_in[6];
    const float* bo = (const float*)d_in[7];
    const float* ln0g = (const float*)d_in[8];
    const float* ln0b = (const float*)d_in[9];
    const float* ln1g = (const float*)d_in[10];
    const float* ln1b = (const float*)d_in[11];
    const float* W1 = (const float*)d_in[12];
    const float* b1 = (const float*)d_in[13];
    const float* W2 = (const float*)d_in[14];
    const float* b2 = (const float*)d_in[15];
    const float* ln2g = (const float*)d_in[16];
    const float* ln2b = (const float*)d_in[17];
    const int* esrc = (const int*)d_in[18];
    const int* edst = (const int*)d_in[19];
    const int* erel = (const int*)d_in[20];
    float* out = (float*)d_out;

    float *p_hsnorm, *p_t1, *p_out, *p_f, *p_score, *p_T, *p_term1;
    __half *p_hsnorm_h, *p_q_h, *p_k_h, *p_v_h, *p_o_h, *p_out_h, *p_h1_h, *p_wn_h;
    __half *p_wq_h, *p_wk_h, *p_wv_h, *p_wo_h, *p_w1_h, *p_w2_h, *p_rel_t_h;
    cudaGetSymbolAddress((void**)&p_hsnorm, g_hsnorm);
    cudaGetSymbolAddress((void**)&p_hsnorm_h, g_hsnorm_h);
    cudaGetSymbolAddress((void**)&p_q_h, g_q_h);
    cudaGetSymbolAddress((void**)&p_k_h, g_k_h);
    cudaGetSymbolAddress((void**)&p_v_h, g_v_h);
    cudaGetSymbolAddress((void**)&p_o_h, g_o_h);
    cudaGetSymbolAddress((void**)&p_t1, g_t1);
    cudaGetSymbolAddress((void**)&p_out, g_out);
    cudaGetSymbolAddress((void**)&p_out_h, g_out_h);
    cudaGetSymbolAddress((void**)&p_h1_h, g_h1_h);
    cudaGetSymbolAddress((void**)&p_f, g_f);
    cudaGetSymbolAddress((void**)&p_score, g_score);
    cudaGetSymbolAddress((void**)&p_T, g_T);
    cudaGetSymbolAddress((void**)&p_term1, g_term1);
    cudaGetSymbolAddress((void**)&p_wn_h, g_wn_h);
    cudaGetSymbolAddress((void**)&p_wq_h, g_wq_h);
    cudaGetSymbolAddress((void**)&p_wk_h, g_wk_h);
    cudaGetSymbolAddress((void**)&p_wv_h, g_wv_h);
    cudaGetSymbolAddress((void**)&p_wo_h, g_wo_h);
    cudaGetSymbolAddress((void**)&p_w1_h, g_w1_h);
    cudaGetSymbolAddress((void**)&p_w2_h, g_w2_h);
    cudaGetSymbolAddress((void**)&p_rel_t_h, g_rel_t_h);

    cudaFuncSetAttribute((const void*)gemm_uni<false, false>,
                         cudaFuncAttributeMaxDynamicSharedMemorySize, GEMM_SMEM);
    cudaFuncSetAttribute((const void*)gemm_uni<false, true>,
                         cudaFuncAttributeMaxDynamicSharedMemorySize, GEMM_SMEM);
    cudaFuncSetAttribute((const void*)gemm_uni<true, true>,
                         cudaFuncAttributeMaxDynamicSharedMemorySize, GEMM_SMEM);
    cudaFuncSetAttribute((const void*)gemm_uni_qkv,
                         cudaFuncAttributeMaxDynamicSharedMemorySize, GEMM_SMEM);

    // 0. weight transposes (fp32 [K,N] -> fp16 [N,K]) + rel transpose
    dim3 tb(32, 8);
    transpose_f2h<<<dim3(D_ / 32, D_ / 32), tb>>>(Wq, p_wq_h, D_, D_);
    transpose_f2h<<<dim3(D_ / 32, D_ / 32), tb>>>(Wk, p_wk_h, D_, D_);
    transpose_f2h<<<dim3(D_ / 32, D_ / 32), tb>>>(Wv, p_wv_h, D_, D_);
    transpose_f2h<<<dim3(D_ / 32, D_ / 32), tb>>>(Wo, p_wo_h, D_, D_);
    transpose_f2h<<<dim3(DF_ / 32, D_ / 32), tb>>>(W1, p_w1_h, D_, DF_);
    transpose_f2h<<<dim3(D_ / 32, DF_ / 32), tb>>>(W2, p_w2_h, DF_, D_);
    rel_transpose<<<(D_ * R_) / 256, 256>>>(rel_tab);

    // 1. ln0
    ln_dual_kernel<<<M_, 256>>>(hidden, ln0g, ln0b, p_hsnorm, p_hsnorm_h);

    // 2. fused Q,K,V GEMMs -> fp16
    QKVArgs qkv;
    qkv.Bt[0] = p_wq_h; qkv.Bt[1] = p_wk_h; qkv.Bt[2] = p_wv_h;
    qkv.bias[0] = bq; qkv.bias[1] = nullptr; qkv.bias[2] = nullptr;
    qkv.C[0] = p_q_h; qkv.C[1] = p_k_h; qkv.C[2] = p_v_h;
    dim3 gQKV(D_ / 128, M_ / 128, 3);
    gemm_uni_qkv<<<gQKV, 128, GEMM_SMEM>>>(p_hsnorm_h, qkv, M_, D_, D_);

    // 3. T = q @ rel^T  [M, 64]
    gemm_T64<<<dim3(1, M_ / 128), 256>>>(p_q_h, p_rel_t_h, p_T, D_);

    // 4. edge scores
    score_kernel<<<(B_ * E_) / 4, dim3(32, 4)>>>(p_q_h, p_k_h, p_T, esrc, edst, erel, p_score);

    // 5. deterministic binning by dst
    zero_cnt_kernel<<<(B_ * L_) / 256, 256>>>();
    hist_kernel<<<(B_ * E_) / 256, 256>>>(edst);
    scan_kernel<<<B_, L_>>>();
    fill_block_kernel<<<512, 256>>>(edst);

    // 6. agg1 + Wn
    agg1_kernel<<<dim3(L_, B_), 256>>>(p_v_h, esrc, p_score);
    wn_kernel<<<dim3(L_, B_), 64>>>(erel, p_score);

    // 7. o = Wn @ rel + term1  (K=64; Bt = rel_t [1024 rows, 64 k])
    dim3 gD(D_ / 128, M_ / 128);
    gemm_uni<false, true><<<gD, 128, GEMM_SMEM>>>(
        p_wn_h, p_rel_t_h, nullptr, p_term1, nullptr, p_o_h, M_, D_, R_);

    // 8. t1 = hs_norm + o @ Wo + bo ; ln1 -> out (dual)
    gemm_uni<false, false><<<gD, 128, GEMM_SMEM>>>(
        p_o_h, p_wo_h, bo, p_hsnorm, p_t1, nullptr, M_, D_, D_);
    ln_dual_kernel<<<M_, 256>>>(p_t1, ln1g, ln1b, p_out, p_out_h);

    // 9. FFN
    dim3 gDF(DF_ / 128, M_ / 128);
    gemm_uni<true, true><<<gDF, 128, GEMM_SMEM>>>(
        p_out_h, p_w1_h, b1, nullptr, nullptr, p_h1_h, M_, DF_, D_);
    gemm_uni<false, false><<<gD, 128, GEMM_SMEM>>>(
        p_h1_h, p_w2_h, b2, p_out, p_f, nullptr, M_, D_, DF_);

    // 10. final
    ln_elu_res_kernel<<<M_, 256>>>(p_f, ln2g, ln2b, hidden, out);
}

// round 11
// speedup vs baseline: 1.2981x; 1.2981x over previous
#include <cuda_runtime.h>
#include <cuda_fp16.h>
#include <math.h>

// Problem constants
#define B_  4
#define L_  1024
#define D_  1024
#define DF_ 4096
#define E_  32768
#define R_  64
#define M_  (B_ * L_)
#define EPS_ 1e-6f

// ---------------------------------------------------------------------------
// Scratch
// ---------------------------------------------------------------------------
__device__ float  g_hsnorm[M_ * D_];
__device__ __half g_hsnorm_h[M_ * D_];
__device__ __half g_q_h[M_ * D_];
__device__ __half g_k_h[M_ * D_];
__device__ __half g_v_h[M_ * D_];
__device__ __half g_o_h[M_ * D_];
__device__ float  g_t1[M_ * D_];
__device__ float  g_out[M_ * D_];
__device__ __half g_out_h[M_ * D_];
__device__ __half g_h1_h[M_ * DF_];
__device__ float  g_f[M_ * D_];
__device__ float  g_score[B_ * E_];
__device__ int    g_perm[B_ * E_];
__device__ int    g_cnt[B_ * L_];
__device__ int    g_off[B_ * (L_ + 1)];
// edge-phase algebra buffers
__device__ float  g_T[M_ * R_];
__device__ float  g_term1[M_ * D_];
__device__ __half g_wn_h[M_ * R_];
// fp16 weights + tables
__device__ __half g_wq_h[D_ * D_];
__device__ __half g_wk_h[D_ * D_];
__device__ __half g_wv_h[D_ * D_];
__device__ __half g_wo_h[D_ * D_];
__device__ __half g_w1_h[D_ * DF_];
__device__ __half g_w2_h[DF_ * D_];
__device__ __half g_rel_h[R_ * D_];    // [r][d] row-major: B for o-GEMM (K=64)
__device__ __half g_rel_t_h[D_ * R_];  // [d][r]: B for T64 GEMM

// ---------------------------------------------------------------------------
// Batched fp32 -> fp16 convert: 7 segments, one launch
// ---------------------------------------------------------------------------
#define NSEG 7
struct CvtArgs {
    const float* src[NSEG];
    __half* dst[NSEG];
    int n[NSEG];
    int cum[NSEG];
};

__global__ void cvt_f2h_multi(CvtArgs a) {
    int blk = blockIdx.x;
    int seg = 0;
    #pragma unroll
    for (int i = 1; i < NSEG; i++) if (blk >= a.cum[i]) seg = i;
    int i = ((blk - a.cum[seg]) * 256 + threadIdx.x) * 8;
    if (i >= a.n[seg]) return;
    const float* x = a.src[seg];
    float4 v0 = *(const float4*)(x + i);
    float4 v1 = *(const float4*)(x + i + 4);
    __half2 h[4];
    h[0] = __floats2half2_rn(v0.x, v0.y);
    h[1] = __floats2half2_rn(v0.z, v0.w);
    h[2] = __floats2half2_rn(v1.x, v1.y);
    h[3] = __floats2half2_rn(v1.z, v1.w);
    *(uint4*)(a.dst[seg] + i) = *(uint4*)h;
}

__global__ void rel_transpose(const float* __restrict__ rel) {
    int idx = blockIdx.x * 256 + threadIdx.x;
    int k = idx >> 6, n = idx & 63;
    g_rel_t_h[idx] = __float2half(rel[n * D_ + k]);
}

// ---------------------------------------------------------------------------
// LayerNorm helpers
// ---------------------------------------------------------------------------
__device__ __forceinline__ void row_moments(float4 v, float& mean, float& rstd,
                                            float* sh1, float* sh2) {
    float s  = v.x + v.y + v.z + v.w;
    float sq = v.x * v.x + v.y * v.y + v.z * v.z + v.w * v.w;
    #pragma unroll
    for (int o = 16; o; o >>= 1) {
        s  += __shfl_xor_sync(0xffffffffu, s, o);
        sq += __shfl_xor_sync(0xffffffffu, sq, o);
    }
    int warp = threadIdx.x >> 5, lane = threadIdx.x & 31;
    if (lane == 0) { sh1[warp] = s; sh2[warp] = sq; }
    __syncthreads();
    if (threadIdx.x < 8) {
        s = sh1[threadIdx.x]; sq = sh2[threadIdx.x];
        #pragma unroll
        for (int o = 4; o; o >>= 1) {
            s  += __shfl_xor_sync(0xffu, s, o);
            sq += __shfl_xor_sync(0xffu, sq, o);
        }
        if (threadIdx.x == 0) { sh1[0] = s; sh2[0] = sq; }
    }
    __syncthreads();
    mean = sh1[0] * (1.0f / D_);
    float var = sh2[0] * (1.0f / D_) - mean * mean;
    rstd = rsqrtf(var + EPS_);
}

__global__ void ln_dual_kernel(const float* __restrict__ x, const float* __restrict__ g,
                               const float* __restrict__ b, float* __restrict__ y,
                               __half* y16) {
    __shared__ float sh1[8], sh2[8];
    size_t row = blockIdx.x;
    int t = threadIdx.x;
    float4 v = ((const float4*)(x + row * D_))[t];
    float mean, rstd;
    row_moments(v, mean, rstd, sh1, sh2);
    float4 gv = ((const float4*)g)[t];
    float4 bv = ((const float4*)b)[t];
    float4 o;
    o.x = (v.x - mean) * rstd * gv.x + bv.x;
    o.y = (v.y - mean) * rstd * gv.y + bv.y;
    o.z = (v.z - mean) * rstd * gv.z + bv.z;
    o.w = (v.w - mean) * rstd * gv.w + bv.w;
    ((float4*)(y + row * D_))[t] = o;
    if (y16) {
        __half2 h0 = __floats2half2_rn(o.x, o.y);
        __half2 h1 = __floats2half2_rn(o.z, o.w);
        __half2* p = (__half2*)(y16 + row * D_);
        p[2 * t] = h0; p[2 * t + 1] = h1;
    }
}

__global__ void ln_elu_res_kernel(const float* __restrict__ x, const float* __restrict__ g,
                                  const float* __restrict__ b,
                                  const float* __restrict__ hidden,
                                  float* __restrict__ out) {
    __shared__ float sh1[8], sh2[8];
    size_t row = blockIdx.x;
    int t = threadIdx.x;
    float4 v = ((const float4*)(x + row * D_))[t];
    float mean, rstd;
    row_moments(v, mean, rstd, sh1, sh2);
    float4 gv = ((const float4*)g)[t];
    float4 bv = ((const float4*)b)[t];
    float4 hv = ((const float4*)(hidden + row * D_))[t];
    float n0 = (v.x - mean) * rstd * gv.x + bv.x;
    float n1 = (v.y - mean) * rstd * gv.y + bv.y;
    float n2 = (v.z - mean) * rstd * gv.z + bv.z;
    float n3 = (v.w - mean) * rstd * gv.w + bv.w;
    float4 o;
    o.x = hv.x + (n0 > 0.f ? n0 : expm1f(n0));
    o.y = hv.y + (n1 > 0.f ? n1 : expm1f(n1));
    o.z = hv.z + (n2 > 0.f ? n2 : expm1f(n2));
    o.w = hv.w + (n3 > 0.f ? n3 : expm1f(n3));
    ((float4*)(out + row * D_))[t] = o;
}

// ---------------------------------------------------------------------------
// FP16 tensor-core GEMM (R8 config): CTA 128x128, 8 warps (2x4), warp 64x32,
// BK=32, 3-stage cp.async, 2 CTAs/SM, ldmatrix for A (non-trans) + B (trans).
// ---------------------------------------------------------------------------
__device__ __forceinline__ void mma_f16(float* c, const unsigned* a, const unsigned* b) {
    asm volatile(
        "mma.sync.aligned.m16n8k16.row.col.f32.f16.f16.f32 "
        "{%0,%1,%2,%3}, {%4,%5,%6,%7}, {%8,%9}, {%0,%1,%2,%3};"
        : "+f"(c[0]), "+f"(c[1]), "+f"(c[2]), "+f"(c[3])
        : "r"(a[0]), "r"(a[1]), "r"(a[2]), "r"(a[3]), "r"(b[0]), "r"(b[1]));
}

#define CP16(dst, src) \
    asm volatile("cp.async.cg.shared.global [%0], [%1], 16;\n" :: "r"(dst), "l"(src))

#define APW   20                     // A pitch, 32-bit words (40 halves)
#define ASTG  (128 * APW)            // 2560 words / stage
#define PBHN  136                    // B pitch in fp16 (272 B, ≡16 mod 128)
#define BSTGW (32 * PBHN / 2)        // 2176 words / stage
#define NSTAGE 3
#define GEMM_SMEM_BYTES (NSTAGE * (ASTG + BSTGW) * 4)   // 56832

template <bool RELU, bool OUTHALF>
__device__ __forceinline__ void gemm_body_h(
    unsigned* sm, const __half* __restrict__ A, const __half* __restrict__ Bm,
    const float* bias, const float* res, float* C32, __half* C16,
    int N, int K, int bm, int bn) {
    unsigned* As = sm;
    unsigned* Bs = sm + NSTAGE * ASTG;
    int tid = threadIdx.x;
    int warp = tid >> 5, lane = tid & 31;
    int g = lane >> 2, tg = lane & 3;
    int wm = (warp & 1) * 64, wn = (warp >> 1) * 32;

    int arow = tid >> 1;
    const __half* aptr = A + (size_t)(bm + arow) * K + (tid & 1) * 16;
    unsigned a_dst = (unsigned)__cvta_generic_to_shared(As + arow * APW + (tid & 1) * 8);
    int brow = tid >> 3, bc = (tid & 7) * 16;
    const __half* bptr = Bm + (size_t)brow * N + bn + bc;
    unsigned b_dst = (unsigned)__cvta_generic_to_shared((__half*)Bs + brow * PBHN + bc);

    // ldmatrix lane bases
    int quad = lane >> 3, j = lane & 7;
    int lrow = (quad & 1) * 8 + j;
    int lcol = wn + (quad >> 1) * 8;
    unsigned b_frag_base = (unsigned)__cvta_generic_to_shared((__half*)Bs + lrow * PBHN + lcol);
    unsigned a_frag_base = (unsigned)__cvta_generic_to_shared(
        (__half*)As + lrow * (APW * 2) + (quad >> 1) * 8);

    int ntiles = K >> 5;

    #pragma unroll
    for (int s = 0; s < NSTAGE - 1; s++) {
        const __half* ap = aptr + s * 32;
        const __half* bp = bptr + (size_t)s * 32 * N;
        unsigned ad = a_dst + s * ASTG * 4;
        unsigned bd = b_dst + s * BSTGW * 4;
        CP16(ad, ap); CP16(ad + 16, ap + 8);
        CP16(bd, bp); CP16(bd + 16, bp + 8);
        asm volatile("cp.async.commit_group;\n");
    }

    float acc[4][4][4];
    #pragma unroll
    for (int mt = 0; mt < 4; mt++)
        #pragma unroll
        for (int nt = 0; nt < 4; nt++)
            #pragma unroll
            for (int r = 0; r < 4; r++) acc[mt][nt][r] = 0.f;

    for (int kt = 0; kt < ntiles; kt++) {
        asm volatile("cp.async.wait_group %0;\n" :: "n"(NSTAGE - 2));
        __syncthreads();

        int nx = kt + NSTAGE - 1;
        if (nx < ntiles) {
            int st = nx % NSTAGE;
            const __half* ap = aptr + nx * 32;
            const __half* bp = bptr + (size_t)nx * 32 * N;
            unsigned ad = a_dst + st * ASTG * 4;
            unsigned bd = b_dst + st * BSTGW * 4;
            CP16(ad, ap); CP16(ad + 16, ap + 8);
            CP16(bd, bp); CP16(bd + 16, bp + 8);
        }
        asm volatile("cp.async.commit_group;\n");

        int cur = kt % NSTAGE;
        unsigned asm_base = a_frag_base + cur * ASTG * 4 + wm * APW * 4;
        unsigned bsm = b_frag_base + cur * BSTGW * 4;
        #pragma unroll
        for (int ks = 0; ks < 2; ks++) {
            unsigned af[4][4];
            #pragma unroll
            for (int mt = 0; mt < 4; mt++) {
                unsigned aaddr = asm_base + mt * 16 * APW * 4 + ks * 32;
                asm volatile(
                    "ldmatrix.sync.aligned.m8n8.x4.shared.b16 {%0,%1,%2,%3}, [%4];"
                    : "=r"(af[mt][0]), "=r"(af[mt][1]), "=r"(af[mt][2]), "=r"(af[mt][3])
                    : "r"(aaddr));
            }
            unsigned bf[4][2];
            #pragma unroll
            for (int nb = 0; nb < 2; nb++) {
                unsigned addr = bsm + ks * 16 * (PBHN * 2) + nb * 32;
                asm volatile(
                    "ldmatrix.sync.aligned.m8n8.x4.trans.shared.b16 {%0,%1,%2,%3}, [%4];"
                    : "=r"(bf[2 * nb][0]), "=r"(bf[2 * nb][1]),
                      "=r"(bf[2 * nb + 1][0]), "=r"(bf[2 * nb + 1][1])
                    : "r"(addr));
            }
            #pragma unroll
            for (int mt = 0; mt < 4; mt++)
                #pragma unroll
                for (int nt = 0; nt < 4; nt++)
                    mma_f16(acc[mt][nt], af[mt], bf[nt]);
        }
    }

    #pragma unroll
    for (int mt = 0; mt < 4; mt++) {
        #pragma unroll
        for (int nt = 0; nt < 4; nt++) {
            int col = bn + wn + nt * 8 + tg * 2;
            #pragma unroll
            for (int h = 0; h < 2; h++) {
                int row = bm + wm + mt * 16 + g + h * 8;
                float vx = acc[mt][nt][2 * h];
                float vy = acc[mt][nt][2 * h + 1];
                if (bias) {
                    float2 bb = *(const float2*)(bias + col);
                    vx += bb.x; vy += bb.y;
                }
                if (res) {
                    float2 rr = *(const float2*)(res + (size_t)row * N + col);
                    vx += rr.x; vy += rr.y;
                }
                if (RELU) { vx = fmaxf(vx, 0.f); vy = fmaxf(vy, 0.f); }
                if (OUTHALF)
                    *(__half2*)(C16 + (size_t)row * N + col) = __floats2half2_rn(vx, vy);
                else
                    *(float2*)(C32 + (size_t)row * N + col) = make_float2(vx, vy);
            }
        }
    }
}

template <bool RELU, bool OUTHALF>
__global__ __launch_bounds__(256, 2) void mma_gemm_h(
    const __half* __restrict__ A, const __half* __restrict__ Bm,
    const float* bias, const float* res, float* C32, __half* C16,
    int M, int N, int K) {
    extern __shared__ unsigned sm[];
    gemm_body_h<RELU, OUTHALF>(sm, A, Bm, bias, res, C32, C16, N, K,
                               blockIdx.y * 128, blockIdx.x * 128);
}

struct QKVArgs {
    const __half* Bm[3];
    const float* bias[3];
    __half* C[3];
};

__global__ __launch_bounds__(256, 2) void mma_gemm_qkv(
    const __half* __restrict__ A, QKVArgs args, int M, int N, int K) {
    extern __shared__ unsigned sm[];
    int z = blockIdx.z;
    gemm_body_h<false, true>(sm, A, args.Bm[z], args.bias[z], nullptr, nullptr,
                             args.C[z], N, K, blockIdx.y * 128, blockIdx.x * 128);
}

// ---------------------------------------------------------------------------
// Small-N GEMM (mma.sync): T[M,64] = q[M,1024] @ rel_t[1024,64]  (fp32 out)
// ---------------------------------------------------------------------------
#define PB64 72
#define BSTG64 (32 * PB64 / 2)

__global__ __launch_bounds__(256, 2) void gemm_T64(
    const __half* __restrict__ A, const __half* __restrict__ Bm,
    float* __restrict__ C, int K) {
    __shared__ unsigned smT[NSTAGE * (ASTG + BSTG64)];
    unsigned* As = smT;
    unsigned* Bs = smT + NSTAGE * ASTG;
    const int N = R_;
    int tid = threadIdx.x;
    int warp = tid >> 5, lane = tid & 31;
    int g = lane >> 2, tg = lane & 3;
    int wm = (warp & 3) * 32, wn = (warp >> 2) * 32;
    int bm = blockIdx.y * 128;

    int arow = tid >> 1;
    const __half* aptr = A + (size_t)(bm + arow) * K + (tid & 1) * 16;
    unsigned a_dst = (unsigned)__cvta_generic_to_shared(As + arow * APW + (tid & 1) * 8);
    int brow = tid >> 3, bc = (tid & 7) * 8;
    const __half* bptr = Bm + (size_t)brow * N + bc;
    unsigned b_dst = (unsigned)__cvta_generic_to_shared((__half*)Bs + brow * PB64 + bc);

    int quad = lane >> 3, j = lane & 7;
    int lrow = (quad & 1) * 8 + j;
    int lcol = wn + (quad >> 1) * 8;
    unsigned b_frag_base = (unsigned)__cvta_generic_to_shared((__half*)Bs + lrow * PB64 + lcol);

    int ntiles = K >> 5;
    #pragma unroll
    for (int s = 0; s < NSTAGE - 1; s++) {
        unsigned ad = a_dst + s * ASTG * 4;
        unsigned bd = b_dst + s * BSTG64 * 4;
        CP16(ad, aptr + s * 32); CP16(ad + 16, aptr + s * 32 + 8);
        CP16(bd, bptr + (size_t)s * 32 * N);
        asm volatile("cp.async.commit_group;\n");
    }

    float acc[2][4][4];
    #pragma unroll
    for (int mt = 0; mt < 2; mt++)
        #pragma unroll
        for (int nt = 0; nt < 4; nt++)
            #pragma unroll
            for (int r = 0; r < 4; r++) acc[mt][nt][r] = 0.f;

    for (int kt = 0; kt < ntiles; kt++) {
        asm volatile("cp.async.wait_group %0;\n" :: "n"(NSTAGE - 2));
        __syncthreads();
        int nx = kt + NSTAGE - 1;
        if (nx < ntiles) {
            int st = nx % NSTAGE;
            unsigned ad = a_dst + st * ASTG * 4;
            unsigned bd = b_dst + st * BSTG64 * 4;
            CP16(ad, aptr + nx * 32); CP16(ad + 16, aptr + nx * 32 + 8);
            CP16(bd, bptr + (size_t)nx * 32 * N);
        }
        asm volatile("cp.async.commit_group;\n");

        int cur = kt % NSTAGE;
        const unsigned* Ab = As + cur * ASTG;
        unsigned bsm = b_frag_base + cur * BSTG64 * 4;
        #pragma unroll
        for (int ks = 0; ks < 2; ks++) {
            unsigned af[2][4];
            #pragma unroll
            for (int mt = 0; mt < 2; mt++) {
                const unsigned* p = Ab + (wm + mt * 16 + g) * APW + ks * 8 + tg;
                af[mt][0] = p[0];
                af[mt][1] = p[8 * APW];
                af[mt][2] = p[4];
                af[mt][3] = p[8 * APW + 4];
            }
            unsigned bf[4][2];
            #pragma unroll
            for (int nb = 0; nb < 2; nb++) {
                unsigned addr = bsm + ks * 16 * (PB64 * 2) + nb * 32;
                asm volatile(
                    "ldmatrix.sync.aligned.m8n8.x4.trans.shared.b16 {%0,%1,%2,%3}, [%4];"
                    : "=r"(bf[2 * nb][0]), "=r"(bf[2 * nb][1]),
                      "=r"(bf[2 * nb + 1][0]), "=r"(bf[2 * nb + 1][1])
                    : "r"(addr));
            }
            #pragma unroll
            for (int mt = 0; mt < 2; mt++)
                #pragma unroll
                for (int nt = 0; nt < 4; nt++)
                    mma_f16(acc[mt][nt], af[mt], bf[nt]);
        }
    }

    #pragma unroll
    for (int mt = 0; mt < 2; mt++)
        #pragma unroll
        for (int nt = 0; nt < 4; nt++) {
            int col = wn + nt * 8 + tg * 2;
            #pragma unroll
            for (int h = 0; h < 2; h++) {
                int row = bm + wm + mt * 16 + g + h * 8;
                *(float2*)(C + (size_t)row * N + col) =
                    make_float2(acc[mt][nt][2 * h], acc[mt][nt][2 * h + 1]);
            }
        }
}

// ---------------------------------------------------------------------------
// Edge scores: k[src].q[dst] + T[dst,rel]
// ---------------------------------------------------------------------------
__global__ void score_kernel(const __half* __restrict__ Q, const __half* __restrict__ Km,
                             const float* __restrict__ T,
                             const int* __restrict__ src, const int* __restrict__ dst,
                             const int* __restrict__ rel, float* __restrict__ score) {
    int idx = blockIdx.x * 4 + threadIdx.y;
    int b = idx >> 15;
    int lane = threadIdx.x;
    int s = src[idx], d = dst[idx], r = rel[idx];
    const __half* kr = Km + ((size_t)b * L_ + s) * D_;
    const __half* qr = Q + ((size_t)b * L_ + d) * D_;
    float acc = 0.f;
    #pragma unroll
    for (int i = 0; i < 4; i++) {
        int c = (lane + 32 * i) * 8;
        uint4 kv = *(const uint4*)(kr + c);
        uint4 qv = *(const uint4*)(qr + c);
        const __half2* kh = (const __half2*)&kv;
        const __half2* qh = (const __half2*)&qv;
        #pragma unroll
        for (int j = 0; j < 4; j++) {
            float2 kf = __half22float2(kh[j]);
            float2 qf = __half22float2(qh[j]);
            acc = fmaf(kf.x, qf.x, acc);
            acc = fmaf(kf.y, qf.y, acc);
        }
    }
    #pragma unroll
    for (int o = 16; o; o >>= 1) acc += __shfl_xor_sync(0xffffffffu, acc, o);
    if (lane == 0) {
        float sc = (acc + T[((size_t)b * L_ + d) * R_ + r]) * 0.03125f;
        sc = fminf(fmaxf(sc, -10.f), 10.f);
        score[idx] = expf(sc);
    }
}

// ---------------------------------------------------------------------------
// Deterministic binning
// ---------------------------------------------------------------------------
__global__ void zero_cnt_kernel() {
    int i = blockIdx.x * 256 + threadIdx.x;
    if (i < B_ * L_) g_cnt[i] = 0;
}

__global__ void hist_kernel(const int* __restrict__ edge_dst) {
    int idx = blockIdx.x * 256 + threadIdx.x;
    if (idx < B_ * E_) atomicAdd(&g_cnt[(idx >> 15) * L_ + edge_dst[idx]], 1);
}

__global__ void scan_kernel() {
    int b = blockIdx.x, t = threadIdx.x;
    __shared__ int s[L_];
    int c = g_cnt[b * L_ + t];
    s[t] = c;
    __syncthreads();
    for (int off = 1; off < L_; off <<= 1) {
        int v = (t >= off) ? s[t - off] : 0;
        __syncthreads();
        s[t] += v;
        __syncthreads();
    }
    g_off[b * (L_ + 1) + t] = s[t] - c;
    if (t == L_ - 1) g_off[b * (L_ + 1) + L_] = s[t];
}

__global__ void fill_block_kernel(const int* __restrict__ edge_dst) {
    __shared__ int sd[1024];
    int b = blockIdx.x >> 7;
    int nodebase = (blockIdx.x & 127) * 8;
    int warp = threadIdx.x >> 5, lane = threadIdx.x & 31;
    int node = nodebase + warp;
    int w = g_off[b * (L_ + 1) + node];
    int* pb = g_perm + b * E_;
    const int* dv = edge_dst + b * E_;
    for (int base = 0; base < E_; base += 1024) {
        __syncthreads();
        #pragma unroll
        for (int i = 0; i < 4; i++) sd[threadIdx.x + 256 * i] = dv[base + threadIdx.x + 256 * i];
        __syncthreads();
        for (int c = 0; c < 1024; c += 32) {
            int d = sd[c + lane];
            unsigned m = __ballot_sync(0xffffffffu, d == node);
            if (d == node) pb[w + __popc(m & ((1u << lane) - 1))] = base + c + lane;
            w += __popc(m);
        }
    }
}

// ---------------------------------------------------------------------------
// Fused aggregation: term1 = (sum s*v[src])/z  AND  Wn[r] = (sum_{rel=r} s)/z.
// Every thread accumulates the identical z in the main loop; threads 0..63
// then re-scan the (cache-hot) bin for the per-rel histogram. Deterministic:
// both passes visit edges in stable perm order.
// ---------------------------------------------------------------------------
__global__ void agg_fused_kernel(const __half* __restrict__ V,
                                 const int* __restrict__ src,
                                 const int* __restrict__ rel,
                                 const float* __restrict__ score) {
    int node = blockIdx.x, b = blockIdx.y;
    int t = threadIdx.x;
    int beg = g_off[b * (L_ + 1) + node];
    int end = g_off[b * (L_ + 1) + node + 1];
    const int* pb = g_perm + b * E_;
    float4 acc = make_float4(0.f, 0.f, 0.f, 0.f);
    float z = 0.f;
    for (int i = beg; i < end; i++) {
        int e = pb[i];
        float s = score[b * E_ + e];
        int sn = src[b * E_ + e];
        uint2 vw = *(const uint2*)(V + ((size_t)b * L_ + sn) * D_ + 4 * t);
        const __half2* vh = (const __half2*)&vw;
        float2 v0 = __half22float2(vh[0]), v1 = __half22float2(vh[1]);
        acc.x = fmaf(s, v0.x, acc.x);
        acc.y = fmaf(s, v0.y, acc.y);
        acc.z = fmaf(s, v1.x, acc.z);
        acc.w = fmaf(s, v1.y, acc.w);
        z += s;
    }
    float inv = 1.0f / z;
    *(float4*)(g_term1 + ((size_t)b * L_ + node) * D_ + 4 * t) =
        make_float4(acc.x * inv, acc.y * inv, acc.z * inv, acc.w * inv);

    // per-rel histogram (threads 0..63, rel t each), same stable order
    if (t < R_) {
        float W = 0.f;
        for (int i = beg; i < end; i++) {
            int e = pb[i];
            if (rel[b * E_ + e] == t) W += score[b * E_ + e];
        }
        g_wn_h[((size_t)b * L_ + node) * R_ + t] = __float2half(W * inv);
    }
}

// ---------------------------------------------------------------------------
// Launch
// ---------------------------------------------------------------------------
extern "C" void kernel_launch(void* const* d_in, const int* in_sizes, int n_in,
                              void* d_out, int out_size) {
    const float* hidden  = (const float*)d_in[0];
    const float* rel_tab = (const float*)d_in[1];
    const float* Wq = (const float*)d_in[2];
    const float* bq = (const float*)d_in[3];
    const float* Wk = (const float*)d_in[4];
    const float* Wv = (const float*)d_in[5];
    const float* Wo = (const float*)d_in[6];
    const float* bo = (const float*)d_in[7];
    const float* ln0g = (const float*)d_in[8];
    const float* ln0b = (const float*)d_in[9];
    const float* ln1g = (const float*)d_in[10];
    const float* ln1b = (const float*)d_in[11];
    const float* W1 = (const float*)d_in[12];
    const float* b1 = (const float*)d_in[13];
    const float* W2 = (const float*)d_in[14];
    const float* b2 = (const float*)d_in[15];
    const float* ln2g = (const float*)d_in[16];
    const float* ln2b = (const float*)d_in[17];
    const int* esrc = (const int*)d_in[18];
    const int* edst = (const int*)d_in[19];
    const int* erel = (const int*)d_in[20];
    float* out = (float*)d_out;

    float *p_hsnorm, *p_t1, *p_out, *p_f, *p_score, *p_T, *p_term1;
    __half *p_hsnorm_h, *p_q_h, *p_k_h, *p_v_h, *p_o_h, *p_out_h, *p_h1_h, *p_wn_h;
    __half *p_wq_h, *p_wk_h, *p_wv_h, *p_wo_h, *p_w1_h, *p_w2_h, *p_rel_h, *p_rel_t_h;
    cudaGetSymbolAddress((void**)&p_hsnorm, g_hsnorm);
    cudaGetSymbolAddress((void**)&p_hsnorm_h, g_hsnorm_h);
    cudaGetSymbolAddress((void**)&p_q_h, g_q_h);
    cudaGetSymbolAddress((void**)&p_k_h, g_k_h);
    cudaGetSymbolAddress((void**)&p_v_h, g_v_h);
    cudaGetSymbolAddress((void**)&p_o_h, g_o_h);
    cudaGetSymbolAddress((void**)&p_t1, g_t1);
    cudaGetSymbolAddress((void**)&p_out, g_out);
    cudaGetSymbolAddress((void**)&p_out_h, g_out_h);
    cudaGetSymbolAddress((void**)&p_h1_h, g_h1_h);
    cudaGetSymbolAddress((void**)&p_f, g_f);
    cudaGetSymbolAddress((void**)&p_score, g_score);
    cudaGetSymbolAddress((void**)&p_T, g_T);
    cudaGetSymbolAddress((void**)&p_term1, g_term1);
    cudaGetSymbolAddress((void**)&p_wn_h, g_wn_h);
    cudaGetSymbolAddress((void**)&p_wq_h, g_wq_h);
    cudaGetSymbolAddress((void**)&p_wk_h, g_wk_h);
    cudaGetSymbolAddress((void**)&p_wv_h, g_wv_h);
    cudaGetSymbolAddress((void**)&p_wo_h, g_wo_h);
    cudaGetSymbolAddress((void**)&p_w1_h, g_w1_h);
    cudaGetSymbolAddress((void**)&p_w2_h, g_w2_h);
    cudaGetSymbolAddress((void**)&p_rel_h, g_rel_h);
    cudaGetSymbolAddress((void**)&p_rel_t_h, g_rel_t_h);

    cudaFuncSetAttribute((const void*)mma_gemm_h<false, false>,
                         cudaFuncAttributeMaxDynamicSharedMemorySize, GEMM_SMEM_BYTES);
    cudaFuncSetAttribute((const void*)mma_gemm_h<false, true>,
                         cudaFuncAttributeMaxDynamicSharedMemorySize, GEMM_SMEM_BYTES);
    cudaFuncSetAttribute((const void*)mma_gemm_h<true, true>,
                         cudaFuncAttributeMaxDynamicSharedMemorySize, GEMM_SMEM_BYTES);
    cudaFuncSetAttribute((const void*)mma_gemm_qkv,
                         cudaFuncAttributeMaxDynamicSharedMemorySize, GEMM_SMEM_BYTES);

    // 0. conversions
    {
        CvtArgs a;
        const float* srcs[NSEG] = {Wq, Wk, Wv, Wo, W1, W2, rel_tab};
        __half* dsts[NSEG] = {p_wq_h, p_wk_h, p_wv_h, p_wo_h, p_w1_h, p_w2_h, p_rel_h};
        int ns[NSEG] = {D_ * D_, D_ * D_, D_ * D_, D_ * D_, D_ * DF_, DF_ * D_, R_ * D_};
        int cum = 0;
        for (int i = 0; i < NSEG; i++) {
            a.src[i] = srcs[i]; a.dst[i] = dsts[i]; a.n[i] = ns[i];
            a.cum[i] = cum;
            cum += (ns[i] + 2047) / 2048;
        }
        cvt_f2h_multi<<<cum, 256>>>(a);
    }
    rel_transpose<<<(D_ * R_) / 256, 256>>>(rel_tab);

    // 1. ln0
    ln_dual_kernel<<<M_, 256>>>(hidden, ln0g, ln0b, p_hsnorm, p_hsnorm_h);

    // 2. fused Q,K,V GEMMs
    QKVArgs qkv;
    qkv.Bm[0] = p_wq_h; qkv.Bm[1] = p_wk_h; qkv.Bm[2] = p_wv_h;
    qkv.bias[0] = bq; qkv.bias[1] = nullptr; qkv.bias[2] = nullptr;
    qkv.C[0] = p_q_h; qkv.C[1] = p_k_h; qkv.C[2] = p_v_h;
    dim3 gQKV(D_ / 128, M_ / 128, 3);
    mma_gemm_qkv<<<gQKV, 256, GEMM_SMEM_BYTES>>>(p_hsnorm_h, qkv, M_, D_, D_);

    // 3. T = q @ rel^T  [M, 64]
    gemm_T64<<<dim3(1, M_ / 128), 256>>>(p_q_h, p_rel_t_h, p_T, D_);

    // 4. edge scores
    score_kernel<<<(B_ * E_) / 4, dim3(32, 4)>>>(p_q_h, p_k_h, p_T, esrc, edst, erel, p_score);

    // 5. deterministic binning by dst
    zero_cnt_kernel<<<(B_ * L_) / 256, 256>>>();
    hist_kernel<<<(B_ * E_) / 256, 256>>>(edst);
    scan_kernel<<<B_, L_>>>();
    fill_block_kernel<<<512, 256>>>(edst);

    // 6. fused agg (term1 + Wn)
    agg_fused_kernel<<<dim3(L_, B_), 256>>>(p_v_h, esrc, erel, p_score);

    // 7. o = Wn @ rel + term1  (K=64 GEMM; B = rel fp16 [64,1024] row-major)
    dim3 gD(D_ / 128, M_ / 128);
    mma_gemm_h<false, true><<<gD, 256, GEMM_SMEM_BYTES>>>(
        p_wn_h, p_rel_h, nullptr, p_term1, nullptr, p_o_h, M_, D_, R_);

    // 8. t1 = hs_norm + o @ Wo + bo ; ln1 -> out (dual)
    mma_gemm_h<false, false><<<gD, 256, GEMM_SMEM_BYTES>>>(
        p_o_h, p_wo_h, bo, p_hsnorm, p_t1, nullptr, M_, D_, D_);
    ln_dual_kernel<<<M_, 256>>>(p_t1, ln1g, ln1b, p_out, p_out_h);

    // 9. FFN
    dim3 gDF(DF_ / 128, M_ / 128);
    mma_gemm_h<true, true><<<gDF, 256, GEMM_SMEM_BYTES>>>(
        p_out_h, p_w1_h, b1, nullptr, nullptr, p_h1_h, M_, DF_, D_);
    mma_gemm_h<false, false><<<gD, 256, GEMM_SMEM_BYTES>>>(
        p_h1_h, p_w2_h, b2, p_out, p_f, nullptr, M_, D_, DF_);

    // 10. final
    ln_elu_res_kernel<<<M_, 256>>>(p_f, ln2g, ln2b, hidden, out);
}